// round 1
// baseline (speedup 1.0000x reference)
#include <cuda_runtime.h>
#include <cstdint>
#include <cstddef>

// Problem constants
#define Tn    2048
#define Bn    4
#define Cn    512
#define Hn    8
#define DHn   64
#define NREL  33          // 2*CLIP+1
#define Mrows (Tn*Bn)     // 8192
#define QKVN  (3*Cn)      // 1536

// Scratch (static __device__ arrays; no allocations allowed)
__device__ float g_xn[Mrows * Cn];      // layernorm output (m = t*B+b, c)
__device__ float g_qkv[Mrows * QKVN];   // fused qkv output, q pre-scaled
__device__ float g_ao[Mrows * Cn];      // attention output (m, h*64+d)

// ---------------------------------------------------------------------------
// LayerNorm: one warp per row of 512
// ---------------------------------------------------------------------------
__global__ __launch_bounds__(256) void ln_kernel(const float* __restrict__ x,
                                                 const float* __restrict__ gamma,
                                                 const float* __restrict__ beta) {
    int row  = blockIdx.x * blockDim.y + threadIdx.y;
    int lane = threadIdx.x;
    const float* xr = x + (size_t)row * Cn;
    float vals[16];
    float s = 0.f;
#pragma unroll
    for (int i = 0; i < 16; i++) { vals[i] = xr[lane + i * 32]; s += vals[i]; }
#pragma unroll
    for (int o = 16; o; o >>= 1) s += __shfl_xor_sync(0xffffffffu, s, o);
    float mu = s * (1.f / 512.f);
    float v = 0.f;
#pragma unroll
    for (int i = 0; i < 16; i++) { float d = vals[i] - mu; v += d * d; }
#pragma unroll
    for (int o = 16; o; o >>= 1) v += __shfl_xor_sync(0xffffffffu, v, o);
    float inv = rsqrtf(v * (1.f / 512.f) + 1e-5f);
    float* op = g_xn + (size_t)row * Cn;
#pragma unroll
    for (int i = 0; i < 16; i++) {
        int c = lane + i * 32;
        op[c] = (vals[i] - mu) * inv * gamma[c] + beta[c];
    }
}

// ---------------------------------------------------------------------------
// Tiled fp32 GEMM: C[m][n] = dot(A[m,:512], W[n,:512]) + bias[n]
// BM=BN=128, BK=16, 256 threads, 8x8 register tile (split 4+4 halves).
// mode==1: A=g_xn, out=g_qkv (N=1536), scale q (n<512) by 0.125
// mode==0: A=g_ao,  out=param (N=512), plain
// ---------------------------------------------------------------------------
__global__ __launch_bounds__(256) void gemm_kernel(const float* __restrict__ W,
                                                   const float* __restrict__ bias,
                                                   float* __restrict__ outp,
                                                   int N, int mode) {
    __shared__ float As[16][132];
    __shared__ float Bs[16][132];

    const float* A = (mode == 1) ? g_xn : g_ao;
    float* out = (mode == 1) ? g_qkv : outp;

    int m0 = blockIdx.y * 128;
    int n0 = blockIdx.x * 128;
    int tid = threadIdx.x;
    int lrow = tid >> 2;     // 0..63
    int lg4  = tid & 3;      // 0..3
    int ty = tid >> 4;       // 0..15
    int tx = tid & 15;       // 0..15

    float acc[8][8];
#pragma unroll
    for (int i = 0; i < 8; i++)
#pragma unroll
        for (int j = 0; j < 8; j++) acc[i][j] = 0.f;

    for (int k0 = 0; k0 < 512; k0 += 16) {
        float4 a0 = *(const float4*)(A + (size_t)(m0 + lrow) * 512 + k0 + lg4 * 4);
        float4 a1 = *(const float4*)(A + (size_t)(m0 + lrow + 64) * 512 + k0 + lg4 * 4);
        float4 b0 = *(const float4*)(W + (size_t)(n0 + lrow) * 512 + k0 + lg4 * 4);
        float4 b1 = *(const float4*)(W + (size_t)(n0 + lrow + 64) * 512 + k0 + lg4 * 4);
        __syncthreads();
        As[lg4 * 4 + 0][lrow] = a0.x; As[lg4 * 4 + 1][lrow] = a0.y;
        As[lg4 * 4 + 2][lrow] = a0.z; As[lg4 * 4 + 3][lrow] = a0.w;
        As[lg4 * 4 + 0][lrow + 64] = a1.x; As[lg4 * 4 + 1][lrow + 64] = a1.y;
        As[lg4 * 4 + 2][lrow + 64] = a1.z; As[lg4 * 4 + 3][lrow + 64] = a1.w;
        Bs[lg4 * 4 + 0][lrow] = b0.x; Bs[lg4 * 4 + 1][lrow] = b0.y;
        Bs[lg4 * 4 + 2][lrow] = b0.z; Bs[lg4 * 4 + 3][lrow] = b0.w;
        Bs[lg4 * 4 + 0][lrow + 64] = b1.x; Bs[lg4 * 4 + 1][lrow + 64] = b1.y;
        Bs[lg4 * 4 + 2][lrow + 64] = b1.z; Bs[lg4 * 4 + 3][lrow + 64] = b1.w;
        __syncthreads();
#pragma unroll
        for (int kk = 0; kk < 16; kk++) {
            float4 av0 = *(const float4*)&As[kk][ty * 4];
            float4 av1 = *(const float4*)&As[kk][ty * 4 + 64];
            float4 bv0 = *(const float4*)&Bs[kk][tx * 4];
            float4 bv1 = *(const float4*)&Bs[kk][tx * 4 + 64];
            float a_[8] = {av0.x, av0.y, av0.z, av0.w, av1.x, av1.y, av1.z, av1.w};
            float b_[8] = {bv0.x, bv0.y, bv0.z, bv0.w, bv1.x, bv1.y, bv1.z, bv1.w};
#pragma unroll
            for (int i = 0; i < 8; i++)
#pragma unroll
                for (int j = 0; j < 8; j++) acc[i][j] += a_[i] * b_[j];
        }
    }

#pragma unroll
    for (int i = 0; i < 8; i++) {
        int m = m0 + ((i < 4) ? (ty * 4 + i) : (64 + ty * 4 + i - 4));
#pragma unroll
        for (int j = 0; j < 8; j++) {
            int n = n0 + ((j < 4) ? (tx * 4 + j) : (64 + tx * 4 + j - 4));
            float v = acc[i][j] + bias[n];
            if (mode == 1 && n < 512) v *= 0.125f;   // q scale = 1/sqrt(64)
            out[(size_t)m * N + n] = v;
        }
    }
}

// ---------------------------------------------------------------------------
// Flash attention with Shaw relative-position bias.
// Grid: (qblocks=32, bh=32). Block: 256 threads. 64 queries per block,
// streaming 64-key tiles with online softmax. 4x4 register micro-tiles.
// ---------------------------------------------------------------------------
#define ATT_STRIDE 68
#define SMEM_ATTN_BYTES ((4 * 64 * ATT_STRIDE + 64 * 34) * 4)

__global__ __launch_bounds__(256, 2) void attn_kernel(const unsigned char* __restrict__ mask,
                                                      const float* __restrict__ rel_emb) {
    extern __shared__ float sm[];
    float* sq  = sm;                        // [64][68]  q rows (row, d)
    float* skT = sm + 64 * ATT_STRIDE;      // [64][68]  k transposed: (d, col)
    float* sv  = sm + 2 * 64 * ATT_STRIDE;  // [64][68]  v (col, d)
    float* sp  = sm + 3 * 64 * ATT_STRIDE;  // [64][68]  probs (row, col); also rel_emb staging
    float* sqr = sm + 4 * 64 * ATT_STRIDE;  // [64][34]  q . rel_emb

    int qb = blockIdx.x;
    int bh = blockIdx.y;
    int b = bh >> 3, h = bh & 7;
    int tid = threadIdx.x;
    int ty = tid >> 4, tx = tid & 15;

    // load Q tile (64 x 64)
#pragma unroll
    for (int it = 0; it < 16; it++) {
        int idx = tid + it * 256;
        int r = idx >> 6, d = idx & 63;
        int t = qb * 64 + r;
        sq[r * ATT_STRIDE + d] = g_qkv[(size_t)(t * 4 + b) * QKVN + h * 64 + d];
    }
    // stage rel_emb (33x64) into sp
    for (int e = tid; e < NREL * 64; e += 256) sp[e] = rel_emb[e];
    __syncthreads();
    // qr[r][rr] = q_row . rel_emb[rr]
    for (int e = tid; e < 64 * NREL; e += 256) {
        int r = e / NREL, rr = e - r * NREL;
        float a = 0.f;
#pragma unroll
        for (int d = 0; d < 64; d++) a += sq[r * ATT_STRIDE + d] * sp[rr * 64 + d];
        sqr[r * 34 + rr] = a;
    }

    float m_i[4], l_i[4], acc[4][4];
#pragma unroll
    for (int i = 0; i < 4; i++) {
        m_i[i] = -1e30f; l_i[i] = 0.f;
#pragma unroll
        for (int j = 0; j < 4; j++) acc[i][j] = 0.f;
    }

    int qi0 = qb * 64 + ty * 4;
    const unsigned char* mrow = mask + b * Tn;

    for (int kb = 0; kb < 32; kb++) {
        __syncthreads();   // prior phase-2 done with sv/sp; qr phase done (iter 0)
        int kbase = kb * 64;
        // load K (transposed) + V tiles
#pragma unroll
        for (int it = 0; it < 16; it++) {
            int idx = tid + it * 256;
            int r = idx >> 6, d = idx & 63;
            size_t gb = (size_t)((kbase + r) * 4 + b) * QKVN + 512 + h * 64 + d;
            skT[d * ATT_STRIDE + r] = g_qkv[gb];
            sv[r * ATT_STRIDE + d]  = g_qkv[gb + 512];
        }
        __syncthreads();

        // phase 1: s = qr-gather + q @ k^T
        float s[4][4];
#pragma unroll
        for (int i = 0; i < 4; i++)
#pragma unroll
            for (int j = 0; j < 4; j++) {
                int rel = (kbase + tx * 4 + j) - (qi0 + i);
                rel = rel < -16 ? -16 : (rel > 16 ? 16 : rel);
                s[i][j] = sqr[(ty * 4 + i) * 34 + rel + 16];
            }
#pragma unroll 16
        for (int d = 0; d < 64; d++) {
            float4 kv = *(const float4*)&skT[d * ATT_STRIDE + tx * 4];
            float a0 = sq[(ty * 4 + 0) * ATT_STRIDE + d];
            float a1 = sq[(ty * 4 + 1) * ATT_STRIDE + d];
            float a2 = sq[(ty * 4 + 2) * ATT_STRIDE + d];
            float a3 = sq[(ty * 4 + 3) * ATT_STRIDE + d];
            s[0][0] += a0 * kv.x; s[0][1] += a0 * kv.y; s[0][2] += a0 * kv.z; s[0][3] += a0 * kv.w;
            s[1][0] += a1 * kv.x; s[1][1] += a1 * kv.y; s[1][2] += a1 * kv.z; s[1][3] += a1 * kv.w;
            s[2][0] += a2 * kv.x; s[2][1] += a2 * kv.y; s[2][2] += a2 * kv.z; s[2][3] += a2 * kv.w;
            s[3][0] += a3 * kv.x; s[3][1] += a3 * kv.y; s[3][2] += a3 * kv.z; s[3][3] += a3 * kv.w;
        }
        // padding mask
        uchar4 mv = *(const uchar4*)(mrow + kbase + tx * 4);
        if (mv.x) { s[0][0] = s[1][0] = s[2][0] = s[3][0] = -1e30f; }
        if (mv.y) { s[0][1] = s[1][1] = s[2][1] = s[3][1] = -1e30f; }
        if (mv.z) { s[0][2] = s[1][2] = s[2][2] = s[3][2] = -1e30f; }
        if (mv.w) { s[0][3] = s[1][3] = s[2][3] = s[3][3] = -1e30f; }

        // online softmax (row reduce across 16 lanes sharing ty)
#pragma unroll
        for (int i = 0; i < 4; i++) {
            float mx = fmaxf(fmaxf(s[i][0], s[i][1]), fmaxf(s[i][2], s[i][3]));
            mx = fmaxf(mx, __shfl_xor_sync(0xffffffffu, mx, 1));
            mx = fmaxf(mx, __shfl_xor_sync(0xffffffffu, mx, 2));
            mx = fmaxf(mx, __shfl_xor_sync(0xffffffffu, mx, 4));
            mx = fmaxf(mx, __shfl_xor_sync(0xffffffffu, mx, 8));
            float m_new = fmaxf(m_i[i], mx);
            float corr = __expf(m_i[i] - m_new);
            float ls = 0.f;
#pragma unroll
            for (int j = 0; j < 4; j++) {
                float p = __expf(s[i][j] - m_new);
                s[i][j] = p; ls += p;
            }
            ls += __shfl_xor_sync(0xffffffffu, ls, 1);
            ls += __shfl_xor_sync(0xffffffffu, ls, 2);
            ls += __shfl_xor_sync(0xffffffffu, ls, 4);
            ls += __shfl_xor_sync(0xffffffffu, ls, 8);
            l_i[i] = l_i[i] * corr + ls;
            m_i[i] = m_new;
            acc[i][0] *= corr; acc[i][1] *= corr; acc[i][2] *= corr; acc[i][3] *= corr;
        }
#pragma unroll
        for (int i = 0; i < 4; i++)
#pragma unroll
            for (int j = 0; j < 4; j++)
                sp[(ty * 4 + i) * ATT_STRIDE + tx * 4 + j] = s[i][j];
        __syncthreads();

        // phase 2: acc += P @ V  (this thread owns dims tx*4..tx*4+3)
#pragma unroll 8
        for (int j2 = 0; j2 < 64; j2++) {
            float4 v4 = *(const float4*)&sv[j2 * ATT_STRIDE + tx * 4];
            float p0 = sp[(ty * 4 + 0) * ATT_STRIDE + j2];
            float p1 = sp[(ty * 4 + 1) * ATT_STRIDE + j2];
            float p2 = sp[(ty * 4 + 2) * ATT_STRIDE + j2];
            float p3 = sp[(ty * 4 + 3) * ATT_STRIDE + j2];
            acc[0][0] += p0 * v4.x; acc[0][1] += p0 * v4.y; acc[0][2] += p0 * v4.z; acc[0][3] += p0 * v4.w;
            acc[1][0] += p1 * v4.x; acc[1][1] += p1 * v4.y; acc[1][2] += p1 * v4.z; acc[1][3] += p1 * v4.w;
            acc[2][0] += p2 * v4.x; acc[2][1] += p2 * v4.y; acc[2][2] += p2 * v4.z; acc[2][3] += p2 * v4.w;
            acc[3][0] += p3 * v4.x; acc[3][1] += p3 * v4.y; acc[3][2] += p3 * v4.z; acc[3][3] += p3 * v4.w;
        }
    }

    // write attention output in (m, h*64+d) layout
#pragma unroll
    for (int i = 0; i < 4; i++) {
        float inv = 1.f / l_i[i];
        int t = qi0 + i;
        size_t o = (size_t)(t * 4 + b) * Cn + h * 64 + tx * 4;
        g_ao[o + 0] = acc[i][0] * inv;
        g_ao[o + 1] = acc[i][1] * inv;
        g_ao[o + 2] = acc[i][2] * inv;
        g_ao[o + 3] = acc[i][3] * inv;
    }
}

// ---------------------------------------------------------------------------
// Launch
// ---------------------------------------------------------------------------
extern "C" void kernel_launch(void* const* d_in, const int* in_sizes, int n_in,
                              void* d_out, int out_size) {
    const float* x            = (const float*)d_in[0];
    const unsigned char* mask = (const unsigned char*)d_in[1];
    const float* ln_g         = (const float*)d_in[2];
    const float* ln_b         = (const float*)d_in[3];
    const float* w_qkv        = (const float*)d_in[4];
    const float* b_qkv        = (const float*)d_in[5];
    const float* w_out        = (const float*)d_in[6];
    const float* b_out        = (const float*)d_in[7];
    const float* rel_emb      = (const float*)d_in[8];
    float* out                = (float*)d_out;

    // 1) LayerNorm
    ln_kernel<<<Mrows / 8, dim3(32, 8)>>>(x, ln_g, ln_b);

    // 2) fused QKV projection (q pre-scaled)
    gemm_kernel<<<dim3(QKVN / 128, Mrows / 128), 256>>>(w_qkv, b_qkv, nullptr, QKVN, 1);

    // 3) flash attention with relative position bias
    cudaFuncSetAttribute(attn_kernel, cudaFuncAttributeMaxDynamicSharedMemorySize,
                         SMEM_ATTN_BYTES);
    attn_kernel<<<dim3(Tn / 64, Bn * Hn), 256, SMEM_ATTN_BYTES>>>(mask, rel_emb);

    // 4) output projection
    gemm_kernel<<<dim3(Cn / 128, Mrows / 128), 256>>>(w_out, b_out, out, Cn, 0);
}